// round 1
// baseline (speedup 1.0000x reference)
#include <cuda_runtime.h>
#include <cstdint>
#include <math.h>

#define NP 8192   // particles == channels

// ---------------- device scratch (no allocations allowed) ----------------
__device__ float g_state[NP * 3];
__device__ float g_invw[NP];
__device__ int   g_idx[NP];

// ---------------- threefry2x32 (JAX rotation schedule) -------------------
// Partitionable mode: 32-bit draw at flat index n is y0^y1 of the block with
// counter (x0=hi=0, x1=lo=n).
__device__ __forceinline__ uint32_t tf32(uint32_t k0, uint32_t k1, uint32_t n)
{
    uint32_t k2 = k0 ^ k1 ^ 0x1BD11BDAu;
    uint32_t x0 = k0;          // 0 + ks[0]
    uint32_t x1 = n + k1;      // n + ks[1]
#define TFR(r) { x0 += x1; x1 = __funnelshift_l(x1, x1, (r)); x1 ^= x0; }
    TFR(13) TFR(15) TFR(26) TFR(6)
    x0 += k1; x1 += k2 + 1u;
    TFR(17) TFR(29) TFR(16) TFR(24)
    x0 += k2; x1 += k0 + 2u;
    TFR(13) TFR(15) TFR(26) TFR(6)
    x0 += k0; x1 += k1 + 3u;
    TFR(17) TFR(29) TFR(16) TFR(24)
    x0 += k1; x1 += k2 + 4u;
    TFR(13) TFR(15) TFR(26) TFR(6)
    x0 += k2; x1 += k0 + 5u;
#undef TFR
    return x0 ^ x1;
}

// bits -> float in [0,1): exact JAX recipe
__device__ __forceinline__ float bits_to_f01(uint32_t b)
{
    return __uint_as_float(0x3f800000u | (b >> 9)) - 1.0f;
}

// ---------------- kernel A: state transition + process noise -------------
__global__ void k_state(const float* __restrict__ sv,
                        const float* __restrict__ T,
                        const float* __restrict__ Q,
                        uint32_t kn0, uint32_t kn1)
{
    int p = blockIdx.x * blockDim.x + threadIdx.x;
    if (p >= NP) return;

    // 3x3 Cholesky (redundant per-thread; trivial cost)
    float l00 = sqrtf(Q[0]);
    float l10 = Q[3] / l00, l20 = Q[6] / l00;
    float l11 = sqrtf(Q[4] - l10 * l10);
    float l21 = (Q[7] - l20 * l10) / l11;
    float l22 = sqrtf(Q[8] - l20 * l20 - l21 * l21);

    // z ~ N(0,1) via sqrt(2)*erfinv(uniform(-1+eps, 1)), matching jax.random.normal
    float z[3];
#pragma unroll
    for (int d = 0; d < 3; ++d) {
        uint32_t b = tf32(kn0, kn1, (uint32_t)(3 * p + d));
        float f = bits_to_f01(b);
        float val = __fadd_rn(__fmul_rn(f, 2.0f), -0.99999994f); // f*(hi-lo)+lo, no fma
        val = fmaxf(-0.99999994f, val);
        z[d] = 1.41421356237f * erfinvf(val);
    }

    float s0 = sv[3 * p], s1 = sv[3 * p + 1], s2 = sv[3 * p + 2];
    float u0 = T[0] * s0 + T[1] * s1 + T[2] * s2;
    float u1 = T[3] * s0 + T[4] * s1 + T[5] * s2;
    float u2 = T[6] * s0 + T[7] * s1 + T[8] * s2;

    // state = updated + z @ L  (L lower triangular)
    g_state[3 * p + 0] = u0 + z[0] * l00 + z[1] * l10 + z[2] * l20;
    g_state[3 * p + 1] = u1 + z[1] * l11 + z[2] * l21;
    g_state[3 * p + 2] = u2 + z[2] * l22;
}

// ---------------- kernel B: w[a] = sum_b (x[a,b] - F[b].s_a)^2 ------------
// one warp per row a; float4 loads of the contiguous inputs row; F from L1.
__global__ void k_weights(const float* __restrict__ x, const float* __restrict__ F)
{
    int warp = threadIdx.x >> 5, lane = threadIdx.x & 31;
    int a = blockIdx.x * 8 + warp;

    float s0 = g_state[3 * a], s1 = g_state[3 * a + 1], s2 = g_state[3 * a + 2];
    const float4* xrow = reinterpret_cast<const float4*>(x + (size_t)a * NP);
    const float4* Fv   = reinterpret_cast<const float4*>(F); // F is (NP,3) contiguous

    float acc = 0.0f;
#pragma unroll 4
    for (int t = 0; t < NP / 128; ++t) {
        int b4 = t * 32 + lane;                 // float4 index within the row
        float4 xv = __ldg(xrow + b4);
        float4 f0 = __ldg(Fv + 3 * b4 + 0);     // 12 consecutive floats = F rows b..b+3
        float4 f1 = __ldg(Fv + 3 * b4 + 1);
        float4 f2 = __ldg(Fv + 3 * b4 + 2);
        float p0 = f0.x * s0 + f0.y * s1 + f0.z * s2;
        float p1 = f0.w * s0 + f1.x * s1 + f1.y * s2;
        float p2 = f1.z * s0 + f1.w * s1 + f2.x * s2;
        float p3 = f2.y * s0 + f2.z * s1 + f2.w * s2;
        float d0 = xv.x - p0, d1 = xv.y - p1, d2 = xv.z - p2, d3 = xv.w - p3;
        acc = fmaf(d0, d0, acc); acc = fmaf(d1, d1, acc);
        acc = fmaf(d2, d2, acc); acc = fmaf(d3, d3, acc);
    }
#pragma unroll
    for (int o = 16; o; o >>= 1) acc += __shfl_down_sync(0xffffffffu, acc, o);
    if (lane == 0) g_invw[a] = 1.0f / acc;
}

// ---------------- kernel C: categorical via argmin of e_ij / w_j ----------
// argmax_j( -log(-log u_ij) + log w_j ) == argmin_j( (-log u_ij) * (1/w_j) )
__global__ void k_cat(uint32_t kc0, uint32_t kc1)
{
    const int row = blockIdx.x;
    const int t = threadIdx.x;
    float mv = __int_as_float(0x7f800000); // +inf
    int   mi = 0;
    uint32_t nb = (uint32_t)row * (uint32_t)NP + (uint32_t)t;

#pragma unroll 4
    for (int k = 0; k < NP / 256; ++k) {
        int j = t + (k << 8);
        uint32_t b = tf32(kc0, kc1, nb + (uint32_t)(k << 8));
        float f = bits_to_f01(b);
        float u = fmaxf(f, 1.17549435e-38f);   // uniform(tiny, 1)
        float e = -logf(u);                    // Exp(1) variate
        float v = e * __ldg(&g_invw[j]);
        if (v < mv) { mv = v; mi = j; }        // strict <: first index wins
    }

    // block argmin reduce (value, then lower index on exact ties)
    int lane = t & 31, warp = t >> 5;
#pragma unroll
    for (int o = 16; o; o >>= 1) {
        float ov = __shfl_down_sync(0xffffffffu, mv, o);
        int   oi = __shfl_down_sync(0xffffffffu, mi, o);
        if (ov < mv || (ov == mv && oi < mi)) { mv = ov; mi = oi; }
    }
    __shared__ float shv[8];
    __shared__ int   shi[8];
    if (lane == 0) { shv[warp] = mv; shi[warp] = mi; }
    __syncthreads();
    if (warp == 0) {
        float v2 = (lane < 8) ? shv[lane] : __int_as_float(0x7f800000);
        int   i2 = (lane < 8) ? shi[lane] : 0x7fffffff;
#pragma unroll
        for (int o = 4; o; o >>= 1) {
            float ov = __shfl_down_sync(0xffffffffu, v2, o);
            int   oi = __shfl_down_sync(0xffffffffu, i2, o);
            if (ov < v2 || (ov == v2 && oi < i2)) { v2 = ov; i2 = oi; }
        }
        if (lane == 0) g_idx[row] = i2;
    }
}

// ---------------- kernel D: mean of gathered states -----------------------
__global__ void k_mean(float* __restrict__ out)
{
    int t = threadIdx.x;
    float s0 = 0.f, s1 = 0.f, s2 = 0.f;
    for (int k = 0; k < NP / 256; ++k) {
        int id = g_idx[t + (k << 8)];
        s0 += g_state[3 * id];
        s1 += g_state[3 * id + 1];
        s2 += g_state[3 * id + 2];
    }
#pragma unroll
    for (int o = 16; o; o >>= 1) {
        s0 += __shfl_down_sync(0xffffffffu, s0, o);
        s1 += __shfl_down_sync(0xffffffffu, s1, o);
        s2 += __shfl_down_sync(0xffffffffu, s2, o);
    }
    __shared__ float sh[3][8];
    int lane = t & 31, warp = t >> 5;
    if (lane == 0) { sh[0][warp] = s0; sh[1][warp] = s1; sh[2][warp] = s2; }
    __syncthreads();
    if (t == 0) {
        float r0 = 0.f, r1 = 0.f, r2 = 0.f;
#pragma unroll
        for (int w = 0; w < 8; ++w) { r0 += sh[0][w]; r1 += sh[1][w]; r2 += sh[2][w]; }
        out[0] = r0 * (1.0f / NP);
        out[1] = r1 * (1.0f / NP);
        out[2] = r2 * (1.0f / NP);
    }
}

// ---------------- host: key derivation (fold-like split) ------------------
static void h_tf(uint32_t k0, uint32_t k1, uint32_t x0, uint32_t x1,
                 uint32_t& y0, uint32_t& y1)
{
    uint32_t k2 = k0 ^ k1 ^ 0x1BD11BDAu;
    x0 += k0; x1 += k1;
    const int R0[4] = {13, 15, 26, 6}, R1[4] = {17, 29, 16, 24};
    const int* RS[5] = {R0, R1, R0, R1, R0};
    const uint32_t ks[3] = {k0, k1, k2};
    for (int g = 0; g < 5; ++g) {
        for (int q = 0; q < 4; ++q) {
            x0 += x1;
            int r = RS[g][q];
            x1 = (x1 << r) | (x1 >> (32 - r));
            x1 ^= x0;
        }
        x0 += ks[(g + 1) % 3];
        x1 += ks[(g + 2) % 3] + (uint32_t)(g + 1);
    }
    y0 = x0; y1 = x1;
}

extern "C" void kernel_launch(void* const* d_in, const int* in_sizes, int n_in,
                              void* d_out, int out_size)
{
    const float* x  = (const float*)d_in[0];  // inputs (1, C, P)
    const float* sv = (const float*)d_in[1];  // state_vector (P, 3)
    const float* T  = (const float*)d_in[2];  // transition (3, 3)
    const float* Q  = (const float*)d_in[3];  // process noise cov (3, 3)
    const float* F  = (const float*)d_in[4];  // forward_matrix (C, 3)

    // jax.random.split(key(42)) in partitionable (fold-like) mode:
    // child i = threefry(key; counter hi=0, lo=i)
    uint32_t kn0, kn1, kc0, kc1;
    h_tf(0u, 42u, 0u, 0u, kn0, kn1);  // k_noise
    h_tf(0u, 42u, 0u, 1u, kc0, kc1);  // k_cat

    k_state  <<<NP / 256, 256>>>(sv, T, Q, kn0, kn1);
    k_weights<<<NP / 8,   256>>>(x, F);
    k_cat    <<<NP,       256>>>(kc0, kc1);
    k_mean   <<<1,        256>>>((float*)d_out);
}